// round 1
// baseline (speedup 1.0000x reference)
#include <cuda_runtime.h>
#include <math.h>

#define D 512
#define Bsz 16
#define L 2048
#define HID 2048
#define GH 128
#define NTOK (Bsz * L)   // 32768

// ------------------------- scratch (static device globals) -------------------------
__device__ float g_h[(size_t)NTOK * D];      // ln1 out, reused for h2
__device__ float g_gm[(size_t)NTOK * D];     // gelu(conv mix)
__device__ float g_m2[(size_t)NTOK * D];     // mixed2
__device__ float g_x1[(size_t)NTOK * D];     // first residual out
__device__ float g_t[(size_t)NTOK * HID];    // ffn hidden
__device__ float g_wmixT[D * D];
__device__ float g_part[Bsz * 16 * D];       // partial column sums
__device__ float g_gate[Bsz * D];
__device__ float g_taps[D * 7];
__device__ float g_cbias[D];

__device__ __forceinline__ float gelu_exact(float v) {
    return 0.5f * v * (1.0f + erff(v * 0.70710678118654752f));
}

// ------------------------- LayerNorm (one token per block, 128 thr) ----------------
__global__ void ln_kernel(const float* __restrict__ x, const float* __restrict__ g,
                          const float* __restrict__ bb, float* __restrict__ out) {
    int n = blockIdx.x;
    const float* xr = x + (size_t)n * D;
    int t = threadIdx.x;
    float v[4];
    float s = 0.f;
#pragma unroll
    for (int i = 0; i < 4; i++) { v[i] = xr[t + 128 * i]; s += v[i]; }
    __shared__ float red[4];
#pragma unroll
    for (int o = 16; o; o >>= 1) s += __shfl_xor_sync(~0u, s, o);
    if ((t & 31) == 0) red[t >> 5] = s;
    __syncthreads();
    float mean = (red[0] + red[1] + red[2] + red[3]) * (1.f / 512.f);
    float s2 = 0.f;
#pragma unroll
    for (int i = 0; i < 4; i++) { float dd = v[i] - mean; s2 += dd * dd; }
#pragma unroll
    for (int o = 16; o; o >>= 1) s2 += __shfl_xor_sync(~0u, s2, o);
    __syncthreads();
    if ((t & 31) == 0) red[t >> 5] = s2;
    __syncthreads();
    float rstd = rsqrtf((red[0] + red[1] + red[2] + red[3]) * (1.f / 512.f) + 1e-5f);
    float* orow = out + (size_t)n * D;
#pragma unroll
    for (int i = 0; i < 4; i++) {
        int d = t + 128 * i;
        orow[d] = (v[i] - mean) * rstd * g[d] + bb[d];
    }
}

// ------------------------- combine dwconv taps (3,5,7 averaged) --------------------
__global__ void taps_kernel(const float* __restrict__ w3, const float* __restrict__ b3,
                            const float* __restrict__ w5, const float* __restrict__ b5,
                            const float* __restrict__ w7, const float* __restrict__ b7) {
    int d = threadIdx.x;  // 512
#pragma unroll
    for (int j = 0; j < 7; j++) {
        float tv = w7[d * 7 + j];
        if (j >= 1 && j <= 5) tv += w5[d * 5 + (j - 1)];
        if (j >= 2 && j <= 4) tv += w3[d * 3 + (j - 2)];
        g_taps[d * 7 + j] = tv * (1.f / 3.f);
    }
    g_cbias[d] = (b3[d] + b5[d] + b7[d]) * (1.f / 3.f);
}

// ------------------------- conv (7-tap along L) + exact GELU -----------------------
__global__ void conv_kernel(const float* __restrict__ h, float* __restrict__ out) {
    int idx = blockIdx.x * 256 + threadIdx.x;  // over NTOK*D
    int d = idx & (D - 1);
    int n = idx >> 9;
    int l = n & (L - 1);
    float acc = g_cbias[d];
#pragma unroll
    for (int j = 0; j < 7; j++) {
        int lp = l + j - 3;
        if (lp >= 0 && lp < L)
            acc = fmaf(h[(size_t)(n + (j - 3)) * D + d], g_taps[d * 7 + j], acc);
    }
    out[idx] = gelu_exact(acc);
}

// ------------------------- 512x512 transpose ---------------------------------------
__global__ void transpose512(const float* __restrict__ in, float* __restrict__ outp) {
    __shared__ float tile[32][33];
    int x = blockIdx.x * 32 + threadIdx.x;
    int y = blockIdx.y * 32 + threadIdx.y;  // block (32,8)
#pragma unroll
    for (int i = 0; i < 32; i += 8) tile[threadIdx.y + i][threadIdx.x] = in[(y + i) * D + x];
    __syncthreads();
    x = blockIdx.y * 32 + threadIdx.x;
    y = blockIdx.x * 32 + threadIdx.y;
#pragma unroll
    for (int i = 0; i < 32; i += 8) outp[(y + i) * D + x] = tile[threadIdx.x][threadIdx.y + i];
}

// ------------------------- partial column sums over L ------------------------------
__global__ void colsum_kernel(const float* __restrict__ m2) {
    int b = blockIdx.y, chunk = blockIdx.x;  // 16 chunks of 128 rows
    int d = threadIdx.x;                     // 512
    const float* base = m2 + ((size_t)(b * L + chunk * 128)) * D + d;
    float s = 0.f;
#pragma unroll 4
    for (int l = 0; l < 128; l++) s += base[(size_t)l * D];
    g_part[(b * 16 + chunk) * D + d] = s;
}

// ------------------------- gate MLP (tiny) ------------------------------------------
__global__ void gate_kernel(const float* __restrict__ cg_w1, const float* __restrict__ cg_b1,
                            const float* __restrict__ cg_w2, const float* __restrict__ cg_b2) {
    int b = blockIdx.x;   // 16
    int t = threadIdx.x;  // 128
    __shared__ float ct[D];
    __shared__ float hid[GH];
    for (int d = t; d < D; d += 128) {
        float s = 0.f;
#pragma unroll
        for (int c = 0; c < 16; c++) s += g_part[(b * 16 + c) * D + d];
        ct[d] = s * (1.f / (float)L);
    }
    __syncthreads();
    {
        float hv = cg_b1[t];
        for (int d = 0; d < D; d++) hv = fmaf(ct[d], cg_w1[d * GH + t], hv);
        hid[t] = gelu_exact(hv);
    }
    __syncthreads();
    for (int o = t; o < D; o += 128) {
        float s = cg_b2[o];
#pragma unroll 4
        for (int j = 0; j < GH; j++) s = fmaf(hid[j], cg_w2[j * D + o], s);
        g_gate[b * D + o] = 1.f / (1.f + expf(-s));
    }
}

// ------------------------- fp32 SIMT GEMM 128x128x16, 8x8/thread -------------------
// C[M,Nn] = epi( A[M,K] (optionally * gate per (token-batch, k)) @ B[K,Nn] + bias )
// epi 0: +bias ; epi 1: gelu(+bias) ; epi 2: res + (+bias)*scale
__global__ __launch_bounds__(256) void sgemm_kernel(
    const float* __restrict__ A, const float* __restrict__ Bm,
    const float* __restrict__ bias, float* __restrict__ C,
    int M, int Nn, int K, int epi,
    const float* __restrict__ gate,
    const float* __restrict__ res, const float* __restrict__ scale) {
    __shared__ float As[16][128];
    __shared__ float Bs[16][128];
    const int tid = threadIdx.x;
    const int bm = blockIdx.y * 128;
    const int bn = blockIdx.x * 128;
    const int trow = (tid >> 4) << 3;
    const int tcol = (tid & 15) << 3;

    float acc[8][8];
#pragma unroll
    for (int i = 0; i < 8; i++)
#pragma unroll
        for (int j = 0; j < 8; j++) acc[i][j] = 0.f;

    const int arow0 = tid >> 2;        // 0..63
    const int akc = (tid & 3) * 4;     // 0,4,8,12
    const int brow0 = tid >> 5;        // 0..7
    const int bcol = (tid & 31) * 4;

    for (int k0 = 0; k0 < K; k0 += 16) {
#pragma unroll
        for (int hh = 0; hh < 2; hh++) {
            int r = arow0 + hh * 64;
            int gm = bm + r;
            float4 av = *reinterpret_cast<const float4*>(&A[(size_t)gm * K + k0 + akc]);
            if (gate) {
                int bb = gm >> 11;  // token / L
                float4 gv = *reinterpret_cast<const float4*>(&gate[bb * D + k0 + akc]);
                av.x *= gv.x; av.y *= gv.y; av.z *= gv.z; av.w *= gv.w;
            }
            As[akc + 0][r] = av.x;
            As[akc + 1][r] = av.y;
            As[akc + 2][r] = av.z;
            As[akc + 3][r] = av.w;
        }
#pragma unroll
        for (int hh = 0; hh < 2; hh++) {
            int r = brow0 + hh * 8;
            *reinterpret_cast<float4*>(&Bs[r][bcol]) =
                *reinterpret_cast<const float4*>(&Bm[(size_t)(k0 + r) * Nn + bn + bcol]);
        }
        __syncthreads();
#pragma unroll
        for (int kk = 0; kk < 16; kk++) {
            float ar[8], br[8];
#pragma unroll
            for (int i = 0; i < 8; i++) ar[i] = As[kk][trow + i];
#pragma unroll
            for (int j = 0; j < 8; j++) br[j] = Bs[kk][tcol + j];
#pragma unroll
            for (int i = 0; i < 8; i++)
#pragma unroll
                for (int j = 0; j < 8; j++) acc[i][j] = fmaf(ar[i], br[j], acc[i][j]);
        }
        __syncthreads();
    }

#pragma unroll
    for (int i = 0; i < 8; i++) {
        int gm = bm + trow + i;
        size_t off = (size_t)gm * Nn + bn + tcol;
#pragma unroll
        for (int j = 0; j < 8; j++) {
            int gn = bn + tcol + j;
            float v = acc[i][j] + bias[gn];
            if (epi == 1) v = gelu_exact(v);
            else if (epi == 2) v = res[off + j] + v * scale[gn];
            C[off + j] = v;
        }
    }
}

// ------------------------- host launch ---------------------------------------------
extern "C" void kernel_launch(void* const* d_in, const int* in_sizes, int n_in,
                              void* d_out, int out_size) {
    const float* x      = (const float*)d_in[0];
    const float* ln1_g  = (const float*)d_in[1];
    const float* ln1_b  = (const float*)d_in[2];
    const float* w3     = (const float*)d_in[3];
    const float* b3     = (const float*)d_in[4];
    const float* w5     = (const float*)d_in[5];
    const float* b5     = (const float*)d_in[6];
    const float* w7     = (const float*)d_in[7];
    const float* b7     = (const float*)d_in[8];
    const float* wmix   = (const float*)d_in[9];
    const float* bmix   = (const float*)d_in[10];
    const float* cg_w1  = (const float*)d_in[11];
    const float* cg_b1  = (const float*)d_in[12];
    const float* cg_w2  = (const float*)d_in[13];
    const float* cg_b2  = (const float*)d_in[14];
    const float* wout   = (const float*)d_in[15];
    const float* bout   = (const float*)d_in[16];
    const float* ls1    = (const float*)d_in[17];
    const float* ln2_g  = (const float*)d_in[18];
    const float* ln2_b  = (const float*)d_in[19];
    const float* ffn_w1 = (const float*)d_in[20];
    const float* ffn_b1 = (const float*)d_in[21];
    const float* ffn_w2 = (const float*)d_in[22];
    const float* ffn_b2 = (const float*)d_in[23];
    const float* ls2    = (const float*)d_in[24];
    float* out = (float*)d_out;

    void* p;
    cudaGetSymbolAddress(&p, g_h);     float* hbuf  = (float*)p;
    cudaGetSymbolAddress(&p, g_gm);    float* gmbuf = (float*)p;
    cudaGetSymbolAddress(&p, g_m2);    float* m2buf = (float*)p;
    cudaGetSymbolAddress(&p, g_x1);    float* x1buf = (float*)p;
    cudaGetSymbolAddress(&p, g_t);     float* tbuf  = (float*)p;
    cudaGetSymbolAddress(&p, g_wmixT); float* wmT   = (float*)p;
    cudaGetSymbolAddress(&p, g_gate);  float* gate  = (float*)p;

    // 1. LN1
    ln_kernel<<<NTOK, 128>>>(x, ln1_g, ln1_b, hbuf);
    // 2. combined conv taps
    taps_kernel<<<1, 512>>>(w3, b3, w5, b5, w7, b7);
    // 3. conv + gelu
    conv_kernel<<<(NTOK * D) / 256, 256>>>(hbuf, gmbuf);
    // 4. transpose wmix (so GEMM1 is NN)
    transpose512<<<dim3(16, 16), dim3(32, 8)>>>(wmix, wmT);
    // 5. mixed2 = gelu(conv) @ wmix^T + bmix
    sgemm_kernel<<<dim3(D / 128, NTOK / 128), 256>>>(
        gmbuf, wmT, bmix, m2buf, NTOK, D, D, 0, nullptr, nullptr, nullptr);
    // 6. column partial sums (channel token)
    colsum_kernel<<<dim3(16, Bsz), 512>>>(m2buf);
    // 7. gate MLP
    gate_kernel<<<Bsz, 128>>>(cg_w1, cg_b1, cg_w2, cg_b2);
    // 8. x1 = x + ((mixed2*gate) @ wout + bout) * ls1
    sgemm_kernel<<<dim3(D / 128, NTOK / 128), 256>>>(
        m2buf, wout, bout, x1buf, NTOK, D, D, 2, gate, x, ls1);
    // 9. LN2
    ln_kernel<<<NTOK, 128>>>(x1buf, ln2_g, ln2_b, hbuf);
    // 10. t = gelu(h2 @ ffn_w1 + b1)
    sgemm_kernel<<<dim3(HID / 128, NTOK / 128), 256>>>(
        hbuf, ffn_w1, ffn_b1, tbuf, NTOK, HID, D, 1, nullptr, nullptr, nullptr);
    // 11. out = x1 + (t @ ffn_w2 + b2) * ls2
    sgemm_kernel<<<dim3(D / 128, NTOK / 128), 256>>>(
        tbuf, ffn_w2, ffn_b2, out, NTOK, D, HID, 2, nullptr, x1buf, ls2);
}

// round 3
// speedup vs baseline: 4.9009x; 4.9009x over previous
#include <cuda_runtime.h>
#include <cuda_bf16.h>
#include <math.h>
#include <stdint.h>

#define D 512
#define Bsz 16
#define L 2048
#define HID 2048
#define GH 128
#define NTOK (Bsz * L)   // 32768

// ------------------------- scratch (static device globals) -------------------------
__device__ __nv_bfloat16 g_h[(size_t)NTOK * D];    // ln1/ln2 out (bf16 GEMM A)
__device__ __nv_bfloat16 g_gm[(size_t)NTOK * D];   // gelu(conv mix) bf16
__device__ float         g_m2[(size_t)NTOK * D];   // mixed2 fp32
__device__ __nv_bfloat16 g_a2[(size_t)NTOK * D];   // m2*gate bf16
__device__ float         g_x1[(size_t)NTOK * D];   // first residual out fp32
__device__ __nv_bfloat16 g_t[(size_t)NTOK * HID];  // ffn hidden bf16
__device__ __nv_bfloat16 g_wmixB[D * D];           // wmix as [o,c] bf16
__device__ __nv_bfloat16 g_woutT[D * D];           // wout^T  [n,k]
__device__ __nv_bfloat16 g_w1T[HID * D];           // ffn_w1^T [hid,d]
__device__ __nv_bfloat16 g_w2T[D * HID];           // ffn_w2^T [d,hid]
__device__ float g_part[Bsz * 16 * D];
__device__ float g_gate[Bsz * D];
__device__ float g_taps[D * 7];
__device__ float g_cbias[D];

__device__ __forceinline__ float gelu_exact(float v) {
    return 0.5f * v * (1.0f + erff(v * 0.70710678118654752f));
}

__device__ __forceinline__ uint32_t smem_u32(const void* p) {
    uint32_t a;
    asm("{ .reg .u64 t; cvta.to.shared.u64 t, %1; cvt.u32.u64 %0, t; }" : "=r"(a) : "l"(p));
    return a;
}
__device__ __forceinline__ void cpasync16(uint32_t s, const void* g) {
    asm volatile("cp.async.cg.shared.global [%0], [%1], 16;" :: "r"(s), "l"(g));
}
__device__ __forceinline__ void cp_commit() { asm volatile("cp.async.commit_group;"); }
template <int N>
__device__ __forceinline__ void cp_wait() {
    asm volatile("cp.async.wait_group %0;" :: "n"(N));
}
__device__ __forceinline__ void ldmat4(uint32_t* r, uint32_t addr) {
    asm volatile("ldmatrix.sync.aligned.m8n8.x4.shared.b16 {%0,%1,%2,%3}, [%4];"
                 : "=r"(r[0]), "=r"(r[1]), "=r"(r[2]), "=r"(r[3]) : "r"(addr));
}
__device__ __forceinline__ void mma16816(float* c, const uint32_t* a, uint32_t b0,
                                         uint32_t b1) {
    asm volatile(
        "mma.sync.aligned.m16n8k16.row.col.f32.bf16.bf16.f32 "
        "{%0,%1,%2,%3}, {%4,%5,%6,%7}, {%8,%9}, {%0,%1,%2,%3};"
        : "+f"(c[0]), "+f"(c[1]), "+f"(c[2]), "+f"(c[3])
        : "r"(a[0]), "r"(a[1]), "r"(a[2]), "r"(a[3]), "r"(b0), "r"(b1));
}

// ------------------------- LayerNorm (fp32 in -> bf16 out) -------------------------
__global__ void ln_kernel(const float* __restrict__ x, const float* __restrict__ g,
                          const float* __restrict__ bb, __nv_bfloat16* __restrict__ out) {
    int n = blockIdx.x;
    const float* xr = x + (size_t)n * D;
    int t = threadIdx.x;
    float v[4];
    float s = 0.f;
#pragma unroll
    for (int i = 0; i < 4; i++) { v[i] = xr[t + 128 * i]; s += v[i]; }
    __shared__ float red[4];
#pragma unroll
    for (int o = 16; o; o >>= 1) s += __shfl_xor_sync(~0u, s, o);
    if ((t & 31) == 0) red[t >> 5] = s;
    __syncthreads();
    float mean = (red[0] + red[1] + red[2] + red[3]) * (1.f / 512.f);
    float s2 = 0.f;
#pragma unroll
    for (int i = 0; i < 4; i++) { float dd = v[i] - mean; s2 += dd * dd; }
#pragma unroll
    for (int o = 16; o; o >>= 1) s2 += __shfl_xor_sync(~0u, s2, o);
    __syncthreads();
    if ((t & 31) == 0) red[t >> 5] = s2;
    __syncthreads();
    float rstd = rsqrtf((red[0] + red[1] + red[2] + red[3]) * (1.f / 512.f) + 1e-5f);
    __nv_bfloat16* orow = out + (size_t)n * D;
#pragma unroll
    for (int i = 0; i < 4; i++) {
        int d = t + 128 * i;
        orow[d] = __float2bfloat16((v[i] - mean) * rstd * g[d] + bb[d]);
    }
}

// ------------------------- combine dwconv taps -------------------------
__global__ void taps_kernel(const float* __restrict__ w3, const float* __restrict__ b3,
                            const float* __restrict__ w5, const float* __restrict__ b5,
                            const float* __restrict__ w7, const float* __restrict__ b7) {
    int d = threadIdx.x;
#pragma unroll
    for (int j = 0; j < 7; j++) {
        float tv = w7[d * 7 + j];
        if (j >= 1 && j <= 5) tv += w5[d * 5 + (j - 1)];
        if (j >= 2 && j <= 4) tv += w3[d * 3 + (j - 2)];
        g_taps[d * 7 + j] = tv * (1.f / 3.f);
    }
    g_cbias[d] = (b3[d] + b5[d] + b7[d]) * (1.f / 3.f);
}

// ------------------------- conv (7-tap) + exact GELU, bf16 in/out ------------------
__global__ void conv_kernel(const __nv_bfloat16* __restrict__ h,
                            __nv_bfloat16* __restrict__ out) {
    int idx = blockIdx.x * 256 + threadIdx.x;
    int d = idx & (D - 1);
    int n = idx >> 9;
    int l = n & (L - 1);
    float acc = g_cbias[d];
#pragma unroll
    for (int j = 0; j < 7; j++) {
        int lp = l + j - 3;
        if (lp >= 0 && lp < L)
            acc = fmaf(__bfloat162float(h[(size_t)(n + (j - 3)) * D + d]),
                       g_taps[d * 7 + j], acc);
    }
    out[idx] = __float2bfloat16(gelu_exact(acc));
}

// ------------------------- weight transpose+convert / convert ----------------------
__global__ void transconv_kernel(const float* __restrict__ in,
                                 __nv_bfloat16* __restrict__ outp, int R, int C) {
    __shared__ float tile[32][33];
    int x = blockIdx.x * 32 + threadIdx.x;
    int y = blockIdx.y * 32 + threadIdx.y;
#pragma unroll
    for (int i = 0; i < 32; i += 8)
        tile[threadIdx.y + i][threadIdx.x] = in[(size_t)(y + i) * C + x];
    __syncthreads();
    int ox = blockIdx.y * 32 + threadIdx.x;
    int oy = blockIdx.x * 32 + threadIdx.y;
#pragma unroll
    for (int i = 0; i < 32; i += 8)
        outp[(size_t)(oy + i) * R + ox] = __float2bfloat16(tile[threadIdx.x][threadIdx.y + i]);
}
__global__ void convert_kernel(const float* __restrict__ in, __nv_bfloat16* __restrict__ o) {
    int idx = blockIdx.x * 256 + threadIdx.x;
    o[idx] = __float2bfloat16(in[idx]);
}

// ------------------------- partial column sums over L ------------------------------
__global__ void colsum_kernel(const float* __restrict__ m2) {
    int b = blockIdx.y, chunk = blockIdx.x;
    int d = threadIdx.x;
    const float* base = m2 + ((size_t)(b * L + chunk * 128)) * D + d;
    float s = 0.f;
#pragma unroll 4
    for (int l = 0; l < 128; l++) s += base[(size_t)l * D];
    g_part[(b * 16 + chunk) * D + d] = s;
}

// ------------------------- gate MLP (tiny) ------------------------------------------
__global__ void gate_kernel(const float* __restrict__ cg_w1, const float* __restrict__ cg_b1,
                            const float* __restrict__ cg_w2, const float* __restrict__ cg_b2) {
    int b = blockIdx.x;
    int t = threadIdx.x;
    __shared__ float ct[D];
    __shared__ float hid[GH];
    for (int d = t; d < D; d += 128) {
        float s = 0.f;
#pragma unroll
        for (int c = 0; c < 16; c++) s += g_part[(b * 16 + c) * D + d];
        ct[d] = s * (1.f / (float)L);
    }
    __syncthreads();
    {
        float hv = cg_b1[t];
        for (int d = 0; d < D; d++) hv = fmaf(ct[d], cg_w1[d * GH + t], hv);
        hid[t] = gelu_exact(hv);
    }
    __syncthreads();
    for (int o = t; o < D; o += 128) {
        float s = cg_b2[o];
#pragma unroll 4
        for (int j = 0; j < GH; j++) s = fmaf(hid[j], cg_w2[j * D + o], s);
        g_gate[b * D + o] = 1.f / (1.f + expf(-s));
    }
}

// ------------------------- gate multiply -> bf16 A for GEMM2 -----------------------
__global__ void gatemul_kernel(const float* __restrict__ m2,
                               __nv_bfloat16* __restrict__ a2) {
    int idx = blockIdx.x * 256 + threadIdx.x;
    int d = idx & (D - 1);
    int b = idx >> 20;
    a2[idx] = __float2bfloat16(m2[idx] * g_gate[b * D + d]);
}

// ------------------------- HMMA bf16 GEMM 128x128x32, cp.async double buffer -------
// C = epi(A[M,K] @ Bw[N,K]^T + bias)
// epi 0: fp32 +bias ; epi 1: bf16 gelu(+bias) ; epi 2: fp32 res + (+bias)*scale
#define ROWB 80                     // smem bytes per 32-bf16 row (+16B pad)
#define TILEB (128 * ROWB)          // 10240 bytes per tile
#define STAGEB (2 * TILEB)          // A+B per stage

__global__ __launch_bounds__(256) void hgemm_kernel(
    const __nv_bfloat16* __restrict__ A, const __nv_bfloat16* __restrict__ Bw,
    const float* __restrict__ bias, float* __restrict__ Cf,
    __nv_bfloat16* __restrict__ Cb, int M, int Nn, int K, int epi,
    const float* __restrict__ res, const float* __restrict__ scale) {
    __shared__ __align__(16) char smem[2 * STAGEB];

    const int tid = threadIdx.x;
    const int bm = blockIdx.y << 7;
    const int bn = blockIdx.x << 7;
    const uint32_t sbase = smem_u32(smem);

    const int lrow = tid >> 2;       // 0..63 (x2 rounds -> 128 rows)
    const int lc = tid & 3;          // 16B chunk within 64B row

    // ---- async tile loader: A/B rows are K-major, load [128 x 32bf16] each --------
    auto load_stage = [&](int s, int k0) {
        uint32_t st = sbase + s * STAGEB;
#pragma unroll
        for (int i = 0; i < 2; i++) {
            int row = lrow + i * 64;
            uint32_t off = row * ROWB + lc * 16;
            cpasync16(st + off, A + (size_t)(bm + row) * K + k0 + lc * 8);
            cpasync16(st + TILEB + off, Bw + (size_t)(bn + row) * K + k0 + lc * 8);
        }
    };

    const int wid = tid >> 5, lane = tid & 31;
    const int wm = wid & 3;          // 4 warps over M: 32 rows each
    const int wn = wid >> 2;         // 2 warps over N: 64 cols each

    float acc[2][8][4];
#pragma unroll
    for (int mt = 0; mt < 2; mt++)
#pragma unroll
        for (int nt = 0; nt < 8; nt++)
#pragma unroll
            for (int r = 0; r < 4; r++) acc[mt][nt][r] = 0.f;

    const int KT = K >> 5;
    load_stage(0, 0);
    cp_commit();

    // ldmatrix source offsets (within stage)
    const uint32_t a_off = (wm * 32 + (lane & 15)) * ROWB + (lane >> 4) * 16;
    const uint32_t b_off = TILEB + (wn * 64 + (lane >> 4) * 8 + (lane & 7)) * ROWB +
                           ((lane >> 3) & 1) * 16;

    for (int kt = 0; kt < KT; kt++) {
        int s = kt & 1;
        if (kt + 1 < KT) {
            load_stage(s ^ 1, (kt + 1) << 5);
            cp_commit();
            cp_wait<1>();
        } else {
            cp_wait<0>();
        }
        __syncthreads();
        uint32_t st = sbase + s * STAGEB;
#pragma unroll
        for (int kk = 0; kk < 2; kk++) {
            uint32_t a[2][4], b[4][4];
#pragma unroll
            for (int mt = 0; mt < 2; mt++)
                ldmat4(a[mt], st + a_off + mt * 16 * ROWB + kk * 32);
#pragma unroll
            for (int i = 0; i < 4; i++)
                ldmat4(b[i], st + b_off + i * 16 * ROWB + kk * 32);
#pragma unroll
            for (int mt = 0; mt < 2; mt++)
#pragma unroll
                for (int nt = 0; nt < 8; nt++)
                    mma16816(acc[mt][nt], a[mt], b[nt >> 1][(nt & 1) * 2],
                             b[nt >> 1][(nt & 1) * 2 + 1]);
        }
        __syncthreads();
    }

    // ---- epilogue: write straight from accumulators (float2 per fragment row) ----
    const int qrow = lane >> 2;      // 0..7
    const int qcol = (lane & 3) * 2;
#pragma unroll
    for (int mt = 0; mt < 2; mt++) {
#pragma unroll
        for (int nt = 0; nt < 8; nt++) {
            int col = bn + wn * 64 + nt * 8 + qcol;
            float2 bi = *reinterpret_cast<const float2*>(bias + col);
            float2 sc = make_float2(0.f, 0.f);
            if (epi == 2) sc = *reinterpret_cast<const float2*>(scale + col);
#pragma unroll
            for (int half = 0; half < 2; half++) {
                int row = bm + wm * 32 + mt * 16 + qrow + half * 8;
                size_t off = (size_t)row * Nn + col;
                float v0 = acc[mt][nt][half * 2 + 0] + bi.x;
                float v1 = acc[mt][nt][half * 2 + 1] + bi.y;
                if (epi == 0) {
                    *reinterpret_cast<float2*>(Cf + off) = make_float2(v0, v1);
                } else if (epi == 1) {
                    __nv_bfloat162 o;
                    o.x = __float2bfloat16(gelu_exact(v0));
                    o.y = __float2bfloat16(gelu_exact(v1));
                    *reinterpret_cast<__nv_bfloat162*>(Cb + off) = o;
                } else {
                    float2 rv = *reinterpret_cast<const float2*>(res + off);
                    *reinterpret_cast<float2*>(Cf + off) =
                        make_float2(rv.x + v0 * sc.x, rv.y + v1 * sc.y);
                }
            }
        }
    }
}

// ------------------------- host launch ---------------------------------------------
extern "C" void kernel_launch(void* const* d_in, const int* in_sizes, int n_in,
                              void* d_out, int out_size) {
    const float* x      = (const float*)d_in[0];
    const float* ln1_g  = (const float*)d_in[1];
    const float* ln1_b  = (const float*)d_in[2];
    const float* w3     = (const float*)d_in[3];
    const float* b3     = (const float*)d_in[4];
    const float* w5     = (const float*)d_in[5];
    const float* b5     = (const float*)d_in[6];
    const float* w7     = (const float*)d_in[7];
    const float* b7     = (const float*)d_in[8];
    const float* wmix   = (const float*)d_in[9];
    const float* bmix   = (const float*)d_in[10];
    const float* cg_w1  = (const float*)d_in[11];
    const float* cg_b1  = (const float*)d_in[12];
    const float* cg_w2  = (const float*)d_in[13];
    const float* cg_b2  = (const float*)d_in[14];
    const float* wout   = (const float*)d_in[15];
    const float* bout   = (const float*)d_in[16];
    const float* ls1    = (const float*)d_in[17];
    const float* ln2_g  = (const float*)d_in[18];
    const float* ln2_b  = (const float*)d_in[19];
    const float* ffn_w1 = (const float*)d_in[20];
    const float* ffn_b1 = (const float*)d_in[21];
    const float* ffn_w2 = (const float*)d_in[22];
    const float* ffn_b2 = (const float*)d_in[23];
    const float* ls2    = (const float*)d_in[24];
    float* out = (float*)d_out;

    void* p;
    cudaGetSymbolAddress(&p, g_h);     __nv_bfloat16* hbuf  = (__nv_bfloat16*)p;
    cudaGetSymbolAddress(&p, g_gm);    __nv_bfloat16* gmbuf = (__nv_bfloat16*)p;
    cudaGetSymbolAddress(&p, g_m2);    float* m2buf = (float*)p;
    cudaGetSymbolAddress(&p, g_a2);    __nv_bfloat16* a2buf = (__nv_bfloat16*)p;
    cudaGetSymbolAddress(&p, g_x1);    float* x1buf = (float*)p;
    cudaGetSymbolAddress(&p, g_t);     __nv_bfloat16* tbuf  = (__nv_bfloat16*)p;
    cudaGetSymbolAddress(&p, g_wmixB); __nv_bfloat16* wmixB = (__nv_bfloat16*)p;
    cudaGetSymbolAddress(&p, g_woutT); __nv_bfloat16* woutT = (__nv_bfloat16*)p;
    cudaGetSymbolAddress(&p, g_w1T);   __nv_bfloat16* w1T   = (__nv_bfloat16*)p;
    cudaGetSymbolAddress(&p, g_w2T);   __nv_bfloat16* w2T   = (__nv_bfloat16*)p;

    // weight prep
    convert_kernel<<<(D * D) / 256, 256>>>(wmix, wmixB);
    transconv_kernel<<<dim3(D / 32, D / 32), dim3(32, 8)>>>(wout, woutT, D, D);
    transconv_kernel<<<dim3(HID / 32, D / 32), dim3(32, 8)>>>(ffn_w1, w1T, D, HID);
    transconv_kernel<<<dim3(D / 32, HID / 32), dim3(32, 8)>>>(ffn_w2, w2T, HID, D);
    taps_kernel<<<1, 512>>>(w3, b3, w5, b5, w7, b7);

    // 1. LN1 -> bf16
    ln_kernel<<<NTOK, 128>>>(x, ln1_g, ln1_b, hbuf);
    // 2. conv + gelu -> bf16
    conv_kernel<<<(NTOK * D) / 256, 256>>>(hbuf, gmbuf);
    // 3. mixed2 = gelu(conv) @ wmix^T + bmix   (fp32 out)
    hgemm_kernel<<<dim3(D / 128, NTOK / 128), 256>>>(
        gmbuf, wmixB, bmix, m2buf, nullptr, NTOK, D, D, 0, nullptr, nullptr);
    // 4. channel token partial sums + gate MLP
    colsum_kernel<<<dim3(16, Bsz), 512>>>(m2buf);
    gate_kernel<<<Bsz, 128>>>(cg_w1, cg_b1, cg_w2, cg_b2);
    // 5. a2 = bf16(m2 * gate)
    gatemul_kernel<<<(NTOK * D) / 256, 256>>>(m2buf, a2buf);
    // 6. x1 = x + (a2 @ wout + bout) * ls1
    hgemm_kernel<<<dim3(D / 128, NTOK / 128), 256>>>(
        a2buf, woutT, bout, x1buf, nullptr, NTOK, D, D, 2, x, ls1);
    // 7. LN2 -> bf16
    ln_kernel<<<NTOK, 128>>>(x1buf, ln2_g, ln2_b, hbuf);
    // 8. t = gelu(h2 @ ffn_w1 + b1)  (bf16 out)
    hgemm_kernel<<<dim3(HID / 128, NTOK / 128), 256>>>(
        hbuf, w1T, ffn_b1, nullptr, tbuf, NTOK, HID, D, 1, nullptr, nullptr);
    // 9. out = x1 + (t @ ffn_w2 + b2) * ls2
    hgemm_kernel<<<dim3(D / 128, NTOK / 128), 256>>>(
        tbuf, w2T, ffn_b2, out, nullptr, NTOK, D, HID, 2, x1buf, ls2);
}